// round 2
// baseline (speedup 1.0000x reference)
#include <cuda_runtime.h>

// Problem dims
#define N_   32
#define C1   96      // in/out planes
#define CM   384     // mid planes
#define H_   28
#define P_   784     // 28*28
#define NP   25088   // 32*784
#define HP   30      // padded spatial
#define K9   9
#define CW4  (CM/4)  // 96 int32 words of packed int8 channels

// ---------------- device scratch (zero-initialized at module load) ----------------
__device__ float g_bw1[CM * C1];            // scale1[o]*sign(w1)
__device__ float g_scale2[CM];
__device__ float g_scale3[C1];
__device__ int   g_sw2[CM * K9 * CW4];      // int8 signs packed 4/int, [co][k][ci/4]
__device__ int   g_sw3[C1 * CW4];           // [co][ci/4]
__device__ float g_y1[N_ * CM * P_];        // conv1 out, NCHW
__device__ int   g_a1p[N_ * HP * HP * CW4]; // sign(bn1) int8, NHWC padded; borders stay 0
__device__ float g_y2[N_ * CM * P_];        // conv2 out, NCHW
__device__ int   g_a2[N_ * P_ * CW4];       // sign(bn2) int8, NHWC
__device__ float g_y3[N_ * C1 * P_];        // conv3 out, NCHW
__device__ float g_mean[CM];
__device__ float g_istd[CM];

__device__ __forceinline__ float sgnf(float w) {
    return (w > 0.f) ? 1.f : ((w < 0.f) ? -1.f : 0.f);
}
__device__ __forceinline__ char sgn8(float w) {
    return (w > 0.f) ? (char)1 : ((w < 0.f) ? (char)-1 : (char)0);
}

__device__ __forceinline__ float block_reduce_sum(float v) {
    __shared__ float sh[256];
    int tid = threadIdx.x;
    __syncthreads();           // protect against previous use of sh
    sh[tid] = v;
    __syncthreads();
    for (int s = blockDim.x >> 1; s > 0; s >>= 1) {
        if (tid < s) sh[tid] += sh[tid + s];
        __syncthreads();
    }
    return sh[0];
}

// ---------------- weight prep ----------------
__global__ void prep1_kernel(const float* __restrict__ w1) {
    int co = blockIdx.x, tid = threadIdx.x;
    float w = (tid < C1) ? w1[co * C1 + tid] : 0.f;
    float s = block_reduce_sum(fabsf(w));
    float scale = s * (1.f / C1);
    if (tid < C1) g_bw1[co * C1 + tid] = scale * sgnf(w);
}

__global__ void prep2_kernel(const float* __restrict__ w2) {
    int co = blockIdx.x, tid = threadIdx.x;
    float acc = 0.f;
    for (int i = tid; i < CM * K9; i += blockDim.x)
        acc += fabsf(w2[co * CM * K9 + i]);
    float scale = block_reduce_sum(acc) * (1.f / (CM * K9));
    if (tid == 0) g_scale2[co] = scale;
    char* sw = (char*)g_sw2;
    for (int i = tid; i < CM * K9; i += blockDim.x) {
        float w = w2[co * CM * K9 + i];
        int ci = i / K9, k = i - ci * K9;       // source [co][ci][ky][kx]
        sw[(co * K9 + k) * CM + ci] = sgn8(w);  // dest   [co][k][ci]
    }
}

__global__ void prep3_kernel(const float* __restrict__ w3) {
    int co = blockIdx.x, tid = threadIdx.x;
    float acc = 0.f;
    for (int i = tid; i < CM; i += blockDim.x)
        acc += fabsf(w3[co * CM + i]);
    float scale = block_reduce_sum(acc) * (1.f / CM);
    if (tid == 0) g_scale3[co] = scale;
    char* sw = (char*)g_sw3;
    for (int i = tid; i < CM; i += blockDim.x)
        sw[co * CM + i] = sgn8(w3[co * CM + i]);
}

// ---------------- conv1: 1x1, fp32, GEMM 384x96 x 25088 ----------------
// block: 256 thr, tile 32co x 128pix, thread 4co x 4pix (FMA-bound ratio 16 FMA : 8 LDS)
__global__ void __launch_bounds__(256) conv1_kernel(const float* __restrict__ x) {
    extern __shared__ float smf[];
    float* xs = smf;              // [96][128]
    float* ws = smf + C1 * 128;   // [32][96]
    int tid = threadIdx.x;
    int qb  = blockIdx.x * 128;   // flat pixel base (n*784+p), 25088/128 = 196 exact
    int cob = blockIdx.y * 32;

    for (int t = tid; t < C1 * 128; t += 256) {
        int k = t >> 7, pix = t & 127;
        int q = qb + pix;
        int n = q / P_, p = q - n * P_;
        xs[t] = x[(n * C1 + k) * P_ + p];
    }
    for (int t = tid; t < 32 * C1; t += 256)
        ws[t] = g_bw1[cob * C1 + t];
    __syncthreads();

    int pg = tid & 31;   // pixel lane
    int cg = tid >> 5;   // 0..7 co groups of 4
    float acc[4][4] = {};
    for (int k = 0; k < C1; k++) {
        float xv[4], wv[4];
#pragma unroll
        for (int j = 0; j < 4; j++) xv[j] = xs[k * 128 + pg + 32 * j];
#pragma unroll
        for (int i = 0; i < 4; i++) wv[i] = ws[(cg * 4 + i) * C1 + k];
#pragma unroll
        for (int i = 0; i < 4; i++)
#pragma unroll
            for (int j = 0; j < 4; j++) acc[i][j] += wv[i] * xv[j];
    }
#pragma unroll
    for (int j = 0; j < 4; j++) {
        int q = qb + pg + 32 * j;
        int n = q / P_, p = q - n * P_;
#pragma unroll
        for (int i = 0; i < 4; i++)
            g_y1[(n * CM + cob + cg * 4 + i) * P_ + p] = acc[i][j];
    }
}

// ---------------- per-channel batch stats (deterministic tree reduce) ----------------
__global__ void stats1_kernel() {
    int c = blockIdx.x, tid = threadIdx.x;
    float s = 0.f, s2 = 0.f;
    for (int i = tid; i < NP; i += blockDim.x) {
        int n = i / P_, p = i - n * P_;
        float v = g_y1[(n * CM + c) * P_ + p];
        s += v; s2 += v * v;
    }
    float S  = block_reduce_sum(s);
    float S2 = block_reduce_sum(s2);
    if (tid == 0) {
        float m = S * (1.f / NP);
        float var = S2 * (1.f / NP) - m * m;
        g_mean[c] = m;
        g_istd[c] = rsqrtf(var + 1e-5f);
    }
}
__global__ void stats2_kernel() {
    int c = blockIdx.x, tid = threadIdx.x;
    float s = 0.f, s2 = 0.f;
    for (int i = tid; i < NP; i += blockDim.x) {
        int n = i / P_, p = i - n * P_;
        float v = g_y2[(n * CM + c) * P_ + p];
        s += v; s2 += v * v;
    }
    float S  = block_reduce_sum(s);
    float S2 = block_reduce_sum(s2);
    if (tid == 0) {
        float m = S * (1.f / NP);
        float var = S2 * (1.f / NP) - m * m;
        g_mean[c] = m;
        g_istd[c] = rsqrtf(var + 1e-5f);
    }
}
__global__ void stats3_kernel() {
    int c = blockIdx.x, tid = threadIdx.x;
    float s = 0.f, s2 = 0.f;
    for (int i = tid; i < NP; i += blockDim.x) {
        int n = i / P_, p = i - n * P_;
        float v = g_y3[(n * C1 + c) * P_ + p];
        s += v; s2 += v * v;
    }
    float S  = block_reduce_sum(s);
    float S2 = block_reduce_sum(s2);
    if (tid == 0) {
        float m = S * (1.f / NP);
        float var = S2 * (1.f / NP) - m * m;
        g_mean[c] = m;
        g_istd[c] = rsqrtf(var + 1e-5f);
    }
}

// ---------------- bn + sign, NCHW fp32 -> NHWC int8 (smem transpose) ----------------
// grid (28 rows, 12 c-tiles, 32 n), block 256
__global__ void bnsign1_kernel(const float* __restrict__ gamma, const float* __restrict__ beta) {
    __shared__ char ss[32][28];
    int y = blockIdx.x, c0 = blockIdx.y * 32, n = blockIdx.z, tid = threadIdx.x;
    for (int t = tid; t < 32 * 28; t += 256) {
        int c = t / 28, xcol = t - c * 28;
        float v = g_y1[(n * CM + c0 + c) * P_ + y * 28 + xcol];
        float u = (v - g_mean[c0 + c]) * g_istd[c0 + c] * gamma[c0 + c] + beta[c0 + c];
        ss[c][xcol] = sgn8(u);
    }
    __syncthreads();
    char* a1 = (char*)g_a1p;
    int base = ((n * HP + y + 1) * HP + 1) * CM;  // padded row y+1, col offset 1
    for (int t = tid; t < 28 * 32; t += 256) {
        int xcol = t >> 5, c = t & 31;
        a1[base + xcol * CM + c0 + c] = ss[c][xcol];
    }
}
__global__ void bnsign2_kernel(const float* __restrict__ gamma, const float* __restrict__ beta) {
    __shared__ char ss[32][28];
    int y = blockIdx.x, c0 = blockIdx.y * 32, n = blockIdx.z, tid = threadIdx.x;
    for (int t = tid; t < 32 * 28; t += 256) {
        int c = t / 28, xcol = t - c * 28;
        float v = g_y2[(n * CM + c0 + c) * P_ + y * 28 + xcol];
        float u = (v - g_mean[c0 + c]) * g_istd[c0 + c] * gamma[c0 + c] + beta[c0 + c];
        ss[c][xcol] = sgn8(u);
    }
    __syncthreads();
    char* a2 = (char*)g_a2;
    int base = (n * P_ + y * 28) * CM;
    for (int t = tid; t < 28 * 32; t += 256) {
        int xcol = t >> 5, c = t & 31;
        a2[base + xcol * CM + c0 + c] = ss[c][xcol];
    }
}

// ---------------- conv2: 3x3 ternary x ternary via dp4a implicit GEMM ----------------
// block tile: 64co x (4 rows x 28 cols = 112 pix); thread tile 4co x 7pix (28 acc)
// ci chunked 96 at a time (24 int words). smem padded strides kill bank conflicts.
#define COT 64
#define CWC 24             // int words per ci chunk (96 ci)
#define NCHK 4
#define WSTR 218           // 9*24 + 2 pad (4co step -> +8 banks)
#define ISTR 25            // 24 + 1 pad per (row,col) cell

__global__ void __launch_bounds__(256) conv2_kernel() {
    extern __shared__ int smi[];
    int* ws  = smi;                  // [64][WSTR]
    int* ins = smi + COT * WSTR;     // [(6*30)][ISTR]
    int tid  = threadIdx.x;
    int rowb = blockIdx.x * 4;       // output rows rowb..rowb+3  (7 blocks)
    int cob  = blockIdx.y * COT;     // 6 blocks
    int n    = blockIdx.z;

    int cg   = tid >> 4;             // 0..15 -> co = cob + cg*4 + ii
    int pgid = tid & 15;
    int r    = pgid >> 2;            // 0..3 output row in tile
    int colb = (pgid & 3) * 7;       // 7 consecutive cols

    int acc[4][7];
#pragma unroll
    for (int i = 0; i < 4; i++)
#pragma unroll
        for (int j = 0; j < 7; j++) acc[i][j] = 0;

    for (int cc = 0; cc < NCHK; cc++) {
        int cw0 = cc * CWC;
        for (int t = tid; t < COT * K9 * CWC; t += 256) {
            int w = t % CWC; int k = (t / CWC) % K9; int co = t / (CWC * K9);
            ws[co * WSTR + k * CWC + w] = g_sw2[((cob + co) * K9 + k) * CW4 + cw0 + w];
        }
        for (int t = tid; t < 6 * 30 * CWC; t += 256) {
            int w = t % CWC; int col = (t / CWC) % 30; int rr = t / (CWC * 30);
            ins[(rr * 30 + col) * ISTR + w] =
                g_a1p[((n * HP + rowb + rr) * HP + col) * CW4 + cw0 + w];
        }
        __syncthreads();

#pragma unroll
        for (int k9 = 0; k9 < 9; k9++) {
            int ky = k9 / 3, kx = k9 - ky * 3;
            const int* insk = ins + ((r + ky) * 30 + colb + kx) * ISTR;
            const int* wsk  = ws + (cg * 4) * WSTR + k9 * CWC;
#pragma unroll 4
            for (int w = 0; w < CWC; w++) {
                int w0 = wsk[w];
                int w1 = wsk[WSTR + w];
                int w2 = wsk[2 * WSTR + w];
                int w3 = wsk[3 * WSTR + w];
#pragma unroll
                for (int j = 0; j < 7; j++) {
                    int iv = insk[j * ISTR + w];
                    acc[0][j] = __dp4a(iv, w0, acc[0][j]);
                    acc[1][j] = __dp4a(iv, w1, acc[1][j]);
                    acc[2][j] = __dp4a(iv, w2, acc[2][j]);
                    acc[3][j] = __dp4a(iv, w3, acc[3][j]);
                }
            }
        }
        __syncthreads();
    }

    int yy = rowb + r;
#pragma unroll
    for (int ii = 0; ii < 4; ii++) {
        int co = cob + cg * 4 + ii;
        float sc = g_scale2[co];
        float* dst = g_y2 + (n * CM + co) * P_ + yy * 28 + colb;
#pragma unroll
        for (int j = 0; j < 7; j++) dst[j] = sc * (float)acc[ii][j];
    }
}

// ---------------- conv3: 1x1 ternary via dp4a, GEMM 96x384 x 25088 ----------------
// block: 96co x 64pix, thread 6co x 4pix
#define ISTR3 97
__global__ void __launch_bounds__(256) conv3_kernel() {
    extern __shared__ int smi3[];
    int* in2 = smi3;                 // [64][97]
    int* ws3 = smi3 + 64 * ISTR3;    // [96][97]
    int tid = threadIdx.x;
    int qb  = blockIdx.x * 64;       // 392 blocks exact

    for (int t = tid; t < C1 * CW4; t += 256) {
        int co = t / CW4, w = t - co * CW4;
        ws3[co * ISTR3 + w] = g_sw3[t];
    }
    for (int t = tid; t < 64 * CW4; t += 256) {
        int pix = t / CW4, w = t - pix * CW4;
        in2[pix * ISTR3 + w] = g_a2[(qb + pix) * CW4 + w];
    }
    __syncthreads();

    int cg = tid >> 4;      // 0..15 -> co = cg*6 + ii
    int pg = tid & 15;      // pix = pg*4 + j
    int acc[6][4];
#pragma unroll
    for (int i = 0; i < 6; i++)
#pragma unroll
        for (int j = 0; j < 4; j++) acc[i][j] = 0;

    for (int w = 0; w < CW4; w++) {
        int wv[6], iv[4];
#pragma unroll
        for (int i = 0; i < 6; i++) wv[i] = ws3[(cg * 6 + i) * ISTR3 + w];
#pragma unroll
        for (int j = 0; j < 4; j++) iv[j] = in2[(pg * 4 + j) * ISTR3 + w];
#pragma unroll
        for (int i = 0; i < 6; i++)
#pragma unroll
            for (int j = 0; j < 4; j++) acc[i][j] = __dp4a(iv[j], wv[i], acc[i][j]);
    }
#pragma unroll
    for (int j = 0; j < 4; j++) {
        int q = qb + pg * 4 + j;
        int n = q / P_, p = q - n * P_;
#pragma unroll
        for (int i = 0; i < 6; i++) {
            int co = cg * 6 + i;
            g_y3[(n * C1 + co) * P_ + p] = g_scale3[co] * (float)acc[i][j];
        }
    }
}

// ---------------- bn3 + residual ----------------
__global__ void final_kernel(const float* __restrict__ x,
                             const float* __restrict__ g3,
                             const float* __restrict__ b3,
                             float* __restrict__ out) {
    int idx = blockIdx.x * 256 + threadIdx.x;
    if (idx < N_ * C1 * P_) {
        int c = (idx / P_) % C1;
        out[idx] = (g_y3[idx] - g_mean[c]) * g_istd[c] * g3[c] + b3[c] + x[idx];
    }
}

// ---------------- launch ----------------
extern "C" void kernel_launch(void* const* d_in, const int* in_sizes, int n_in,
                              void* d_out, int out_size) {
    const float* x  = (const float*)d_in[0];
    const float* w1 = (const float*)d_in[1];
    const float* g1 = (const float*)d_in[2];
    const float* b1 = (const float*)d_in[3];
    const float* w2 = (const float*)d_in[4];
    const float* g2 = (const float*)d_in[5];
    const float* b2 = (const float*)d_in[6];
    const float* w3 = (const float*)d_in[7];
    const float* g3 = (const float*)d_in[8];
    const float* b3 = (const float*)d_in[9];
    float* out = (float*)d_out;

    const int SM1 = (C1 * 128 + 32 * C1) * 4;                   // 61440
    const int SM2 = (COT * WSTR + 6 * 30 * ISTR) * 4;           // 73808
    const int SM3 = (64 * ISTR3 + C1 * ISTR3) * 4;              // 62080
    cudaFuncSetAttribute(conv1_kernel, cudaFuncAttributeMaxDynamicSharedMemorySize, SM1);
    cudaFuncSetAttribute(conv2_kernel, cudaFuncAttributeMaxDynamicSharedMemorySize, SM2);
    cudaFuncSetAttribute(conv3_kernel, cudaFuncAttributeMaxDynamicSharedMemorySize, SM3);

    prep1_kernel<<<CM, 128>>>(w1);
    prep2_kernel<<<CM, 256>>>(w2);
    prep3_kernel<<<C1, 256>>>(w3);

    conv1_kernel<<<dim3(NP / 128, CM / 32), 256, SM1>>>(x);
    stats1_kernel<<<CM, 256>>>();
    bnsign1_kernel<<<dim3(28, CM / 32, N_), 256>>>(g1, b1);

    conv2_kernel<<<dim3(7, CM / COT, N_), 256, SM2>>>();
    stats2_kernel<<<CM, 256>>>();
    bnsign2_kernel<<<dim3(28, CM / 32, N_), 256>>>(g2, b2);

    conv3_kernel<<<NP / 64, 256, SM3>>>();
    stats3_kernel<<<C1, 256>>>();
    final_kernel<<<(N_ * C1 * P_ + 255) / 256, 256>>>(x, g3, b3, out);
}